// round 14
// baseline (speedup 1.0000x reference)
#include <cuda_runtime.h>
#include <cuda_fp16.h>
#include <cstdint>
#include <cstring>

#define TT 64
#define DD 384
#define NH 8
#define HS 48
#define FFD 1536
#define NQKV 1152
#define NBMAX 2048
#define MROWS (NBMAX*TT)

typedef unsigned long long u64;
typedef unsigned int u32;

// ======================= device scratch buffers =======================
__device__ __half g_wqkv[NQKV*DD];
__device__ __half g_wot[DD*DD];
__device__ __half g_w1t[FFD*DD];
__device__ __half g_w2t[DD*FFD];
__device__ float g_bqkv[NQKV];
__device__ float g_h[(size_t)MROWS*DD];
__device__ __half g_h16[(size_t)MROWS*DD];
__device__ __half g_qkv16[(size_t)MROWS*NQKV];
__device__ __half g_at16[(size_t)MROWS*DD];
__device__ float g_hs[(size_t)MROWS*DD];
__device__ float g_h2[(size_t)MROWS*DD];
__device__ __half g_h216[(size_t)MROWS*DD];
__device__ __half g_r16[(size_t)MROWS*FFD];

// ======================= helpers =======================
__device__ __forceinline__ u32 h2u(float a, float b) {
    __half2 h = __floats2half2_rn(a, b);
    u32 r; memcpy(&r, &h, 4); return r;
}
__device__ __forceinline__ u32 smem_u32(const void* p) {
    u32 a; asm("{ .reg .u64 t; cvta.to.shared.u64 t, %1; cvt.u32.u64 %0, t; }" : "=r"(a) : "l"(p));
    return a;
}
__device__ __forceinline__ void cp16(u32 dst, const void* src) {
    asm volatile("cp.async.cg.shared.global [%0], [%1], 16;" :: "r"(dst), "l"(src));
}
#define CP_COMMIT()  asm volatile("cp.async.commit_group;" ::: "memory")
#define CP_WAIT(n)   asm volatile("cp.async.wait_group %0;" :: "n"(n) : "memory")

__device__ __forceinline__ void ldsm_x4(u32 addr, u32* r) {
    asm volatile("ldmatrix.sync.aligned.m8n8.x4.shared.b16 {%0,%1,%2,%3}, [%4];"
        : "=r"(r[0]), "=r"(r[1]), "=r"(r[2]), "=r"(r[3]) : "r"(addr));
}
__device__ __forceinline__ void ldsm_x4_t(u32 addr, u32* r) {
    asm volatile("ldmatrix.sync.aligned.m8n8.x4.trans.shared.b16 {%0,%1,%2,%3}, [%4];"
        : "=r"(r[0]), "=r"(r[1]), "=r"(r[2]), "=r"(r[3]) : "r"(addr));
}
__device__ __forceinline__ void mma_f16(float* c, const u32* a, const u32* b) {
    asm volatile("mma.sync.aligned.m16n8k16.row.col.f32.f16.f16.f32 "
        "{%0,%1,%2,%3}, {%4,%5,%6,%7}, {%8,%9}, {%0,%1,%2,%3};"
        : "+f"(c[0]), "+f"(c[1]), "+f"(c[2]), "+f"(c[3])
        : "r"(a[0]), "r"(a[1]), "r"(a[2]), "r"(a[3]), "r"(b[0]), "r"(b[1]));
}

// ======================= weight fp16 convert / transpose =======================
__global__ void split_weights_kernel(
    const float* __restrict__ wq, const float* __restrict__ bq,
    const float* __restrict__ wk, const float* __restrict__ bk,
    const float* __restrict__ wv, const float* __restrict__ bv,
    const float* __restrict__ wo, const float* __restrict__ w1,
    const float* __restrict__ w2)
{
    const int stride = gridDim.x * blockDim.x;
    const int t0 = blockIdx.x * blockDim.x + threadIdx.x;
    for (int i = t0; i < NQKV*DD; i += stride) {
        int n = i / DD, k = i - n*DD;
        int h = n / 144, rm = n - h*144, m = rm / 48, e = rm - m*48;
        const float* src = (m==0) ? wq : ((m==1) ? wk : wv);
        g_wqkv[i] = __float2half_rn(src[((size_t)(h*DD + k))*HS + e]);
    }
    for (int i = t0; i < DD*DD; i += stride) {
        int n = i / DD, k = i - n*DD;
        g_wot[i] = __float2half_rn(wo[(size_t)k*DD + n]);
    }
    for (int i = t0; i < FFD*DD; i += stride) {
        int n = i / DD, k = i - n*DD;
        g_w1t[i] = __float2half_rn(w1[(size_t)k*FFD + n]);
    }
    for (int i = t0; i < DD*FFD; i += stride) {
        int n = i / FFD, k = i - n*FFD;
        g_w2t[i] = __float2half_rn(w2[(size_t)k*DD + n]);
    }
    for (int i = t0; i < NQKV; i += stride) {
        int h = i / 144, rm = i - h*144, m = rm / 48, e = rm - m*48;
        g_bqkv[i] = (m==0 ? bq : (m==1 ? bk : bv))[h*HS + e];
    }
}

// ======================= layernorm + fp16 out =======================
__global__ __launch_bounds__(256) void ln_kernel(
    const float* __restrict__ in1,
    const float* __restrict__ gg, const float* __restrict__ bb,
    float* __restrict__ outf, __half* __restrict__ oh,
    int nrows)
{
    int r = blockIdx.x*8 + (threadIdx.x >> 5);
    int l = threadIdx.x & 31;
    if (r >= nrows) return;
    size_t ro = (size_t)r * DD;
    float v[12]; float s1 = 0.f, s2 = 0.f;
    #pragma unroll
    for (int jt = 0; jt < 3; jt++) {
        int c = jt*128 + 4*l;
        float4 a = *(const float4*)(in1 + ro + c);
        v[4*jt+0]=a.x; v[4*jt+1]=a.y; v[4*jt+2]=a.z; v[4*jt+3]=a.w;
    }
    #pragma unroll
    for (int i = 0; i < 12; i++) { s1 += v[i]; s2 += v[i]*v[i]; }
    #pragma unroll
    for (int o = 16; o > 0; o >>= 1) {
        s1 += __shfl_xor_sync(0xffffffffu, s1, o);
        s2 += __shfl_xor_sync(0xffffffffu, s2, o);
    }
    float mean = s1 * (1.0f/384.0f);
    float var  = s2 * (1.0f/384.0f) - mean*mean;
    float rstd = rsqrtf(var + 1e-5f);
    #pragma unroll
    for (int jt = 0; jt < 3; jt++) {
        int c = jt*128 + 4*l;
        float4 gv = *(const float4*)(gg + c);
        float4 bv = *(const float4*)(bb + c);
        float y0 = (v[4*jt+0]-mean)*rstd*gv.x + bv.x;
        float y1 = (v[4*jt+1]-mean)*rstd*gv.y + bv.y;
        float y2 = (v[4*jt+2]-mean)*rstd*gv.z + bv.z;
        float y3 = (v[4*jt+3]-mean)*rstd*gv.w + bv.w;
        if (outf) *(float4*)(outf + ro + c) = make_float4(y0, y1, y2, y3);
        *(__half2*)(oh + ro + c)     = __floats2half2_rn(y0, y1);
        *(__half2*)(oh + ro + c + 2) = __floats2half2_rn(y2, y3);
    }
}

// ======================= fp16 GEMM: 4 warps, 64x64 warp tiles =======================
// mode 0: outf = D + bias
// mode 2: oh = fp16(relu(D + bias))
// mode 3: outf = D + bias + resid
// mode 4: oh = fp16(D + bias)
#define ARR_BYTES 18432                  // 128 rows * 144 B
#define STG_BYTES (2*ARR_BYTES)          // 36864
#define GSM_TOTAL (2*STG_BYTES)          // 73728

__global__ __launch_bounds__(128, 2) void gemm_kernel(
    const __half* __restrict__ Ah, const __half* __restrict__ Bh,
    const float* __restrict__ bias, const float* __restrict__ resid,
    float* __restrict__ outf, __half* __restrict__ oh,
    int K, int Ntiles, int Ntot, int mode)
{
    extern __shared__ char smem[];
    const u32 smem_base = smem_u32(smem);
    const int tid = threadIdx.x;
    const int wid = tid >> 5;
    const int lane = tid & 31;

    const int mt = blockIdx.x / Ntiles;
    const int nt = blockIdx.x - mt * Ntiles;
    const size_t arow = (size_t)mt * 128;
    const size_t brow = (size_t)nt * 128;

    const __half* Abase = Ah + arow * (size_t)K;
    const __half* Bbase = Bh + brow * (size_t)K;

    const int wm = wid & 1;    // 2 m-blocks of 64
    const int wn = wid >> 1;   // 2 n-blocks of 64

    const u32 a_off = (u32)((wm*64 + (lane & 15)) * 144 + (lane >> 4) * 16);
    const u32 b_off = (u32)((wn*64 + ((lane & 7) | ((lane >> 1) & 8))) * 144
                            + ((lane >> 3) & 1) * 16);

    float c[4][8][4];
    #pragma unroll
    for (int mi = 0; mi < 4; mi++)
        #pragma unroll
        for (int ni = 0; ni < 8; ni++)
            #pragma unroll
            for (int j = 0; j < 4; j++) c[mi][ni][j] = 0.f;

    const int nc = K >> 6;   // K/64 chunks

    auto load_chunk = [&](int stage, int cc) {
        const u32 sb = smem_base + stage * STG_BYTES;
        const int c0 = cc << 6;
        #pragma unroll
        for (int i = 0; i < 16; i++) {
            int s = tid + (i << 7);
            int arr = s >> 10;             // 0..1
            int within = s & 1023;
            int r   = within >> 3;
            int c16 = within & 7;
            const __half* bp = (arr == 0) ? Abase : Bbase;
            const void* src = bp + (size_t)r * K + c0 + (c16 << 3);
            u32 dst = sb + arr * ARR_BYTES + (u32)(r * 144 + (c16 << 4));
            cp16(dst, src);
        }
        CP_COMMIT();
    };

    load_chunk(0, 0);
    for (int cc = 0; cc < nc; cc++) {
        const int cur = cc & 1;
        if (cc + 1 < nc) { load_chunk((cc + 1) & 1, cc + 1); CP_WAIT(1); }
        else             { CP_WAIT(0); }
        __syncthreads();

        const u32 sb = smem_base + cur * STG_BYTES;
        const u32 sa = sb + a_off;
        const u32 sbh = sb + ARR_BYTES + b_off;

        #pragma unroll
        for (int ks = 0; ks < 4; ks++) {
            const u32 ko = (u32)(ks * 32);     // 16 cols * 2B
            u32 ah[4][4], bb[4][4];
            #pragma unroll
            for (int mi = 0; mi < 4; mi++)
                ldsm_x4(sa + (u32)(mi * 2304) + ko, ah[mi]);
            #pragma unroll
            for (int nb = 0; nb < 4; nb++)
                ldsm_x4(sbh + (u32)(nb * 2304) + ko, bb[nb]);
            #pragma unroll
            for (int mi = 0; mi < 4; mi++)
                #pragma unroll
                for (int ni = 0; ni < 8; ni++)
                    mma_f16(c[mi][ni], ah[mi], &bb[ni >> 1][(ni & 1) * 2]);
        }
        __syncthreads();
    }

    const int r0 = wm*64 + (lane >> 2);
    const int cc0 = wn*64 + (lane & 3)*2;

    #pragma unroll
    for (int mi = 0; mi < 4; mi++) {
        #pragma unroll
        for (int half = 0; half < 2; half++) {
            const size_t orow = arow + r0 + mi*16 + half*8;
            #pragma unroll
            for (int ni = 0; ni < 8; ni++) {
                const size_t ncol = brow + cc0 + ni*8;
                float v0 = c[mi][ni][half*2+0] + bias[ncol];
                float v1 = c[mi][ni][half*2+1] + bias[ncol+1];
                if (mode == 2) {
                    v0 = fmaxf(v0, 0.f); v1 = fmaxf(v1, 0.f);
                    *(__half2*)(oh + orow*(size_t)Ntot + ncol) = __floats2half2_rn(v0, v1);
                } else if (mode == 4) {
                    *(__half2*)(oh + orow*(size_t)Ntot + ncol) = __floats2half2_rn(v0, v1);
                } else if (mode == 3) {
                    const float* rp = resid + orow*(size_t)Ntot + ncol;
                    float2 o; o.x = v0 + rp[0]; o.y = v1 + rp[1];
                    *(float2*)(outf + orow*(size_t)Ntot + ncol) = o;
                } else {
                    float2 o; o.x = v0; o.y = v1;
                    *(float2*)(outf + orow*(size_t)Ntot + ncol) = o;
                }
            }
        }
    }
}

// ======================= HMMA attention core =======================
#define ATS 112
#define AARR 7168

__global__ __launch_bounds__(128) void attn_kernel()
{
    __shared__ __align__(16) char sm[3*AARR];
    const u32 smb = smem_u32(sm);

    const int tid = threadIdx.x;
    const int wid = tid >> 5;
    const int lane = tid & 31;
    const int bh = blockIdx.x;
    const int b = bh >> 3;
    const int h = bh & 7;
    const float kScale = 0.14433756729740643f;   // 48^-0.5

    {
        const __half* src = g_qkv16 + (size_t)(b*TT) * NQKV + h*144;
        #pragma unroll
        for (int i = 0; i < 9; i++) {
            int s = tid + (i << 7);
            int r = s / 18;
            int j = s - r*18;
            int arr = j / 6;
            int jj = j - arr*6;
            cp16(smb + arr*AARR + r*ATS + jj*16,
                 src + (size_t)r*NQKV + j*8);
        }
        CP_COMMIT(); CP_WAIT(0);
        __syncthreads();
    }

    const u32 smQ = smb, smK = smb + AARR, smV = smb + 2*AARR;

    const u32 a_addr  = smQ + (u32)((16*wid + (lane & 15)) * ATS + (lane >> 4) * 16);
    const u32 kb_addr = smK + (u32)((((lane & 7) | ((lane >> 1) & 8))) * ATS
                                    + ((lane >> 3) & 1) * 16);
    const int vg = lane >> 3;
    const u32 vb_addr = smV + (u32)(((vg & 1) * 8 + (lane & 7)) * ATS + (vg >> 1) * 16);

    float sc[8][4];
    #pragma unroll
    for (int nb = 0; nb < 8; nb++)
        #pragma unroll
        for (int j = 0; j < 4; j++) sc[nb][j] = 0.f;

    {
        u32 aq[3][4];
        #pragma unroll
        for (int ks = 0; ks < 3; ks++) ldsm_x4(a_addr + ks*32, aq[ks]);
        #pragma unroll
        for (int np = 0; np < 4; np++) {
            #pragma unroll
            for (int ks = 0; ks < 3; ks++) {
                u32 bb[4];
                ldsm_x4(kb_addr + (u32)(np*16*ATS) + ks*32, bb);
                mma_f16(sc[2*np],   aq[ks], &bb[0]);
                mma_f16(sc[2*np+1], aq[ks], &bb[2]);
            }
        }
    }

    const int r_lo = 16*wid + (lane >> 2);
    const int c0 = (lane & 3) * 2;
    float mlo = -1e30f, mhi = -1e30f;
    #pragma unroll
    for (int nb = 0; nb < 8; nb++) {
        const int cA = nb*8 + c0, cB = cA + 1;
        if (cA > r_lo)     sc[nb][0] = -1e30f;
        if (cB > r_lo)     sc[nb][1] = -1e30f;
        if (cA > r_lo + 8) sc[nb][2] = -1e30f;
        if (cB > r_lo + 8) sc[nb][3] = -1e30f;
        mlo = fmaxf(mlo, fmaxf(sc[nb][0], sc[nb][1]));
        mhi = fmaxf(mhi, fmaxf(sc[nb][2], sc[nb][3]));
    }
    #pragma unroll
    for (int o = 1; o <= 2; o <<= 1) {
        mlo = fmaxf(mlo, __shfl_xor_sync(0xffffffffu, mlo, o));
        mhi = fmaxf(mhi, __shfl_xor_sync(0xffffffffu, mhi, o));
    }
    mlo *= kScale; mhi *= kScale;
    float slo = 0.f, shi = 0.f;
    #pragma unroll
    for (int nb = 0; nb < 8; nb++) {
        sc[nb][0] = __expf(sc[nb][0]*kScale - mlo);
        sc[nb][1] = __expf(sc[nb][1]*kScale - mlo);
        sc[nb][2] = __expf(sc[nb][2]*kScale - mhi);
        sc[nb][3] = __expf(sc[nb][3]*kScale - mhi);
        slo += sc[nb][0] + sc[nb][1];
        shi += sc[nb][2] + sc[nb][3];
    }
    #pragma unroll
    for (int o = 1; o <= 2; o <<= 1) {
        slo += __shfl_xor_sync(0xffffffffu, slo, o);
        shi += __shfl_xor_sync(0xffffffffu, shi, o);
    }
    const float ilo = 1.0f / slo, ihi = 1.0f / shi;
    #pragma unroll
    for (int nb = 0; nb < 8; nb++) {
        sc[nb][0] *= ilo; sc[nb][1] *= ilo;
        sc[nb][2] *= ihi; sc[nb][3] *= ihi;
    }

    u32 pf[4][4];
    #pragma unroll
    for (int ks = 0; ks < 4; ks++) {
        const int t0 = 2*ks, t1 = 2*ks + 1;
        pf[ks][0] = h2u(sc[t0][0], sc[t0][1]);
        pf[ks][1] = h2u(sc[t0][2], sc[t0][3]);
        pf[ks][2] = h2u(sc[t1][0], sc[t1][1]);
        pf[ks][3] = h2u(sc[t1][2], sc[t1][3]);
    }

    float oc[6][4];
    #pragma unroll
    for (int nb = 0; nb < 6; nb++)
        #pragma unroll
        for (int j = 0; j < 4; j++) oc[nb][j] = 0.f;

    #pragma unroll
    for (int ks = 0; ks < 4; ks++) {
        #pragma unroll
        for (int np = 0; np < 3; np++) {
            u32 vb[4];
            ldsm_x4_t(vb_addr + (u32)(ks*16*ATS) + (u32)(np*32), vb);
            mma_f16(oc[2*np],   pf[ks], &vb[0]);
            mma_f16(oc[2*np+1], pf[ks], &vb[2]);
        }
    }

    #pragma unroll
    for (int nb = 0; nb < 6; nb++) {
        #pragma unroll
        for (int half = 0; half < 2; half++) {
            const int r = r_lo + 8*half;
            const size_t row = (size_t)(b*TT + r);
            const int col = h*HS + nb*8 + c0;
            *(__half2*)(g_at16 + row*DD + col) =
                __floats2half2_rn(oc[nb][half*2+0], oc[nb][half*2+1]);
        }
    }
}

// ======================= host launcher =======================
template <typename T>
static void* sym_addr(T& sym) { void* p = nullptr; cudaGetSymbolAddress(&p, sym); return p; }

extern "C" void kernel_launch(void* const* d_in, const int* in_sizes, int n_in,
                              void* d_out, int out_size) {
    const float* x   = (const float*)d_in[0];
    const float* wq  = (const float*)d_in[1];
    const float* bq  = (const float*)d_in[2];
    const float* wk  = (const float*)d_in[3];
    const float* bk  = (const float*)d_in[4];
    const float* wv  = (const float*)d_in[5];
    const float* bv  = (const float*)d_in[6];
    const float* wo  = (const float*)d_in[7];
    const float* bo  = (const float*)d_in[8];
    const float* w1  = (const float*)d_in[9];
    const float* b1  = (const float*)d_in[10];
    const float* w2  = (const float*)d_in[11];
    const float* b2  = (const float*)d_in[12];
    const float* g1  = (const float*)d_in[13];
    const float* be1 = (const float*)d_in[14];
    const float* g2  = (const float*)d_in[15];
    const float* be2 = (const float*)d_in[16];
    float* out = (float*)d_out;

    const int nb = in_sizes[0] / (TT * DD);
    const int M  = nb * TT;
    const int Mtiles = M / 128;

    float* p_h      = (float*)sym_addr(g_h);
    __half* p_h16   = (__half*)sym_addr(g_h16);
    __half* p_qkv16 = (__half*)sym_addr(g_qkv16);
    __half* p_at16  = (__half*)sym_addr(g_at16);
    float* p_hs     = (float*)sym_addr(g_hs);
    float* p_h2     = (float*)sym_addr(g_h2);
    __half* p_h216  = (__half*)sym_addr(g_h216);
    __half* p_r16   = (__half*)sym_addr(g_r16);
    __half* p_wqkv  = (__half*)sym_addr(g_wqkv);
    __half* p_wot   = (__half*)sym_addr(g_wot);
    __half* p_w1t   = (__half*)sym_addr(g_w1t);
    __half* p_w2t   = (__half*)sym_addr(g_w2t);
    float* p_bqkv   = (float*)sym_addr(g_bqkv);

    cudaFuncSetAttribute(gemm_kernel, cudaFuncAttributeMaxDynamicSharedMemorySize, GSM_TOTAL);

    // 1. weight fp16 convert / transpose
    split_weights_kernel<<<1024, 256>>>(wq, bq, wk, bk, wv, bv, wo, w1, w2);

    // 2. LN1
    ln_kernel<<<M/8, 256>>>(x, g1, be1, p_h, p_h16, M);

    // 3. QKV GEMM
    gemm_kernel<<<Mtiles*9, 128, GSM_TOTAL>>>(
        p_h16, p_wqkv, p_bqkv, nullptr,
        nullptr, p_qkv16, DD, 9, NQKV, 4);

    // 4. HMMA attention core
    attn_kernel<<<nb*NH, 128>>>();

    // 5. wo GEMM with fused attention residual
    gemm_kernel<<<Mtiles*3, 128, GSM_TOTAL>>>(
        p_at16, p_wot, bo, p_h,
        p_hs, nullptr, DD, 3, DD, 3);

    // 6. LN2
    ln_kernel<<<M/8, 256>>>(p_hs, g2, be2, p_h2, p_h216, M);

    // 7. FF1
    gemm_kernel<<<Mtiles*12, 128, GSM_TOTAL>>>(
        p_h216, p_w1t, b1, nullptr,
        nullptr, p_r16, DD, 12, FFD, 2);

    // 8. FF2
    gemm_kernel<<<Mtiles*3, 128, GSM_TOTAL>>>(
        p_r16, p_w2t, b2, p_h2,
        out, nullptr, FFD, 3, DD, 3);
}

// round 16
// speedup vs baseline: 1.0074x; 1.0074x over previous
#include <cuda_runtime.h>
#include <cuda_fp16.h>
#include <cstdint>
#include <cstring>

#define TT 64
#define DD 384
#define NH 8
#define HS 48
#define FFD 1536
#define NQKV 1152
#define NBMAX 2048
#define MROWS (NBMAX*TT)

typedef unsigned long long u64;
typedef unsigned int u32;

// ======================= device scratch buffers =======================
__device__ __half g_wqkv[NQKV*DD];
__device__ __half g_wot[DD*DD];
__device__ __half g_w1t[FFD*DD];
__device__ __half g_w2t[DD*FFD];
__device__ float g_bqkv[NQKV];
__device__ __half g_h16[(size_t)MROWS*DD];
__device__ __half g_qkv16[(size_t)MROWS*NQKV];
__device__ __half g_at16[(size_t)MROWS*DD];
__device__ __half g_hs16[(size_t)MROWS*DD];
__device__ __half g_h216[(size_t)MROWS*DD];
__device__ __half g_r16[(size_t)MROWS*FFD];

// ======================= helpers =======================
__device__ __forceinline__ u32 h2u(float a, float b) {
    __half2 h = __floats2half2_rn(a, b);
    u32 r; memcpy(&r, &h, 4); return r;
}
__device__ __forceinline__ u32 smem_u32(const void* p) {
    u32 a; asm("{ .reg .u64 t; cvta.to.shared.u64 t, %1; cvt.u32.u64 %0, t; }" : "=r"(a) : "l"(p));
    return a;
}
__device__ __forceinline__ void cp16(u32 dst, const void* src) {
    asm volatile("cp.async.cg.shared.global [%0], [%1], 16;" :: "r"(dst), "l"(src));
}
#define CP_COMMIT()  asm volatile("cp.async.commit_group;" ::: "memory")
#define CP_WAIT(n)   asm volatile("cp.async.wait_group %0;" :: "n"(n) : "memory")

__device__ __forceinline__ void ldsm_x4(u32 addr, u32* r) {
    asm volatile("ldmatrix.sync.aligned.m8n8.x4.shared.b16 {%0,%1,%2,%3}, [%4];"
        : "=r"(r[0]), "=r"(r[1]), "=r"(r[2]), "=r"(r[3]) : "r"(addr));
}
__device__ __forceinline__ void ldsm_x4_t(u32 addr, u32* r) {
    asm volatile("ldmatrix.sync.aligned.m8n8.x4.trans.shared.b16 {%0,%1,%2,%3}, [%4];"
        : "=r"(r[0]), "=r"(r[1]), "=r"(r[2]), "=r"(r[3]) : "r"(addr));
}
__device__ __forceinline__ void mma_f16(float* c, const u32* a, const u32* b) {
    asm volatile("mma.sync.aligned.m16n8k16.row.col.f32.f16.f16.f32 "
        "{%0,%1,%2,%3}, {%4,%5,%6,%7}, {%8,%9}, {%0,%1,%2,%3};"
        : "+f"(c[0]), "+f"(c[1]), "+f"(c[2]), "+f"(c[3])
        : "r"(a[0]), "r"(a[1]), "r"(a[2]), "r"(a[3]), "r"(b[0]), "r"(b[1]));
}

// ======================= weight fp16 convert / transpose =======================
__global__ void split_weights_kernel(
    const float* __restrict__ wq, const float* __restrict__ bq,
    const float* __restrict__ wk, const float* __restrict__ bk,
    const float* __restrict__ wv, const float* __restrict__ bv,
    const float* __restrict__ wo, const float* __restrict__ w1,
    const float* __restrict__ w2)
{
    const int stride = gridDim.x * blockDim.x;
    const int t0 = blockIdx.x * blockDim.x + threadIdx.x;
    for (int i = t0; i < NQKV*DD; i += stride) {
        int n = i / DD, k = i - n*DD;
        int h = n / 144, rm = n - h*144, m = rm / 48, e = rm - m*48;
        const float* src = (m==0) ? wq : ((m==1) ? wk : wv);
        g_wqkv[i] = __float2half_rn(src[((size_t)(h*DD + k))*HS + e]);
    }
    for (int i = t0; i < DD*DD; i += stride) {
        int n = i / DD, k = i - n*DD;
        g_wot[i] = __float2half_rn(wo[(size_t)k*DD + n]);
    }
    for (int i = t0; i < FFD*DD; i += stride) {
        int n = i / DD, k = i - n*DD;
        g_w1t[i] = __float2half_rn(w1[(size_t)k*FFD + n]);
    }
    for (int i = t0; i < DD*FFD; i += stride) {
        int n = i / FFD, k = i - n*FFD;
        g_w2t[i] = __float2half_rn(w2[(size_t)k*DD + n]);
    }
    for (int i = t0; i < NQKV; i += stride) {
        int h = i / 144, rm = i - h*144, m = rm / 48, e = rm - m*48;
        g_bqkv[i] = (m==0 ? bq : (m==1 ? bk : bv))[h*HS + e];
    }
}

// ======================= layernorm (fp32 input) -> fp16 =======================
__global__ __launch_bounds__(256) void ln_f32_kernel(
    const float* __restrict__ in1,
    const float* __restrict__ gg, const float* __restrict__ bb,
    __half* __restrict__ oh, int nrows)
{
    int r = blockIdx.x*8 + (threadIdx.x >> 5);
    int l = threadIdx.x & 31;
    if (r >= nrows) return;
    size_t ro = (size_t)r * DD;
    float v[12]; float s1 = 0.f, s2 = 0.f;
    #pragma unroll
    for (int jt = 0; jt < 3; jt++) {
        int c = jt*128 + 4*l;
        float4 a = *(const float4*)(in1 + ro + c);
        v[4*jt+0]=a.x; v[4*jt+1]=a.y; v[4*jt+2]=a.z; v[4*jt+3]=a.w;
    }
    #pragma unroll
    for (int i = 0; i < 12; i++) { s1 += v[i]; s2 += v[i]*v[i]; }
    #pragma unroll
    for (int o = 16; o > 0; o >>= 1) {
        s1 += __shfl_xor_sync(0xffffffffu, s1, o);
        s2 += __shfl_xor_sync(0xffffffffu, s2, o);
    }
    float mean = s1 * (1.0f/384.0f);
    float var  = s2 * (1.0f/384.0f) - mean*mean;
    float rstd = rsqrtf(var + 1e-5f);
    #pragma unroll
    for (int jt = 0; jt < 3; jt++) {
        int c = jt*128 + 4*l;
        float4 gv = *(const float4*)(gg + c);
        float4 bv = *(const float4*)(bb + c);
        float y0 = (v[4*jt+0]-mean)*rstd*gv.x + bv.x;
        float y1 = (v[4*jt+1]-mean)*rstd*gv.y + bv.y;
        float y2 = (v[4*jt+2]-mean)*rstd*gv.z + bv.z;
        float y3 = (v[4*jt+3]-mean)*rstd*gv.w + bv.w;
        *(__half2*)(oh + ro + c)     = __floats2half2_rn(y0, y1);
        *(__half2*)(oh + ro + c + 2) = __floats2half2_rn(y2, y3);
    }
}

// ======================= layernorm (fp16 input) -> fp16 =======================
__global__ __launch_bounds__(256) void ln_f16_kernel(
    const __half* __restrict__ in1,
    const float* __restrict__ gg, const float* __restrict__ bb,
    __half* __restrict__ oh, int nrows)
{
    int r = blockIdx.x*8 + (threadIdx.x >> 5);
    int l = threadIdx.x & 31;
    if (r >= nrows) return;
    size_t ro = (size_t)r * DD;
    float v[12]; float s1 = 0.f, s2 = 0.f;
    #pragma unroll
    for (int jt = 0; jt < 3; jt++) {
        int c = jt*128 + 4*l;
        uint2 raw = *(const uint2*)(in1 + ro + c);
        __half2 a0, a1; memcpy(&a0, &raw.x, 4); memcpy(&a1, &raw.y, 4);
        float2 f0 = __half22float2(a0), f1 = __half22float2(a1);
        v[4*jt+0]=f0.x; v[4*jt+1]=f0.y; v[4*jt+2]=f1.x; v[4*jt+3]=f1.y;
    }
    #pragma unroll
    for (int i = 0; i < 12; i++) { s1 += v[i]; s2 += v[i]*v[i]; }
    #pragma unroll
    for (int o = 16; o > 0; o >>= 1) {
        s1 += __shfl_xor_sync(0xffffffffu, s1, o);
        s2 += __shfl_xor_sync(0xffffffffu, s2, o);
    }
    float mean = s1 * (1.0f/384.0f);
    float var  = s2 * (1.0f/384.0f) - mean*mean;
    float rstd = rsqrtf(var + 1e-5f);
    #pragma unroll
    for (int jt = 0; jt < 3; jt++) {
        int c = jt*128 + 4*l;
        float4 gv = *(const float4*)(gg + c);
        float4 bv = *(const float4*)(bb + c);
        float y0 = (v[4*jt+0]-mean)*rstd*gv.x + bv.x;
        float y1 = (v[4*jt+1]-mean)*rstd*gv.y + bv.y;
        float y2 = (v[4*jt+2]-mean)*rstd*gv.z + bv.z;
        float y3 = (v[4*jt+3]-mean)*rstd*gv.w + bv.w;
        *(__half2*)(oh + ro + c)     = __floats2half2_rn(y0, y1);
        *(__half2*)(oh + ro + c + 2) = __floats2half2_rn(y2, y3);
    }
}

// ======================= fp16 GEMM via mma.sync (R13 config: 8 warps, K-chunk 64) =======================
// mode 2: oh = fp16(relu(D + bias))
// mode 3: outf = D + bias + resid16   (fp32 out)
// mode 4: oh = fp16(D + bias)
// mode 5: oh = fp16(D + bias + resid16)
#define ARR_BYTES 18432                  // 128 rows * 144 B
#define STG_BYTES (2*ARR_BYTES)          // 36864
#define GSM_TOTAL (2*STG_BYTES)          // 73728

__global__ __launch_bounds__(256, 2) void gemm_kernel(
    const __half* __restrict__ Ah, const __half* __restrict__ Bh,
    const float* __restrict__ bias, const __half* __restrict__ resid16,
    float* __restrict__ outf, __half* __restrict__ oh,
    int K, int Ntiles, int Ntot, int mode)
{
    extern __shared__ char smem[];
    const u32 smem_base = smem_u32(smem);
    const int tid = threadIdx.x;
    const int wid = tid >> 5;
    const int lane = tid & 31;

    const int mt = blockIdx.x / Ntiles;
    const int nt = blockIdx.x - mt * Ntiles;
    const size_t arow = (size_t)mt * 128;
    const size_t brow = (size_t)nt * 128;

    const __half* Abase = Ah + arow * (size_t)K;
    const __half* Bbase = Bh + brow * (size_t)K;

    const int wm = wid & 1;
    const int wn = wid >> 1;

    const u32 a_off = (u32)((wm*64 + (lane & 15)) * 144 + (lane >> 4) * 16);
    const u32 b_off = (u32)((wn*32 + ((lane & 7) | ((lane >> 1) & 8))) * 144
                            + ((lane >> 3) & 1) * 16);

    float c[4][4][4];
    #pragma unroll
    for (int mi = 0; mi < 4; mi++)
        #pragma unroll
        for (int ni = 0; ni < 4; ni++)
            #pragma unroll
            for (int j = 0; j < 4; j++) c[mi][ni][j] = 0.f;

    const int nc = K >> 6;

    auto load_chunk = [&](int stage, int cc) {
        const u32 sb = smem_base + stage * STG_BYTES;
        const int c0 = cc << 6;
        #pragma unroll
        for (int i = 0; i < 8; i++) {
            int s = tid + (i << 8);
            int arr = s >> 10;
            int within = s & 1023;
            int r   = within >> 3;
            int c16 = within & 7;
            const __half* bp = (arr == 0) ? Abase : Bbase;
            const void* src = bp + (size_t)r * K + c0 + (c16 << 3);
            u32 dst = sb + arr * ARR_BYTES + (u32)(r * 144 + (c16 << 4));
            cp16(dst, src);
        }
        CP_COMMIT();
    };

    load_chunk(0, 0);
    for (int cc = 0; cc < nc; cc++) {
        const int cur = cc & 1;
        if (cc + 1 < nc) { load_chunk((cc + 1) & 1, cc + 1); CP_WAIT(1); }
        else             { CP_WAIT(0); }
        __syncthreads();

        const u32 sb = smem_base + cur * STG_BYTES;
        const u32 sa = sb + a_off;
        const u32 sbh = sb + ARR_BYTES + b_off;

        #pragma unroll
        for (int ks = 0; ks < 4; ks++) {
            const u32 ko = (u32)(ks * 32);
            u32 ah[4][4], bb[2][4];
            #pragma unroll
            for (int mi = 0; mi < 4; mi++)
                ldsm_x4(sa + (u32)(mi * 2304) + ko, ah[mi]);
            #pragma unroll
            for (int nb = 0; nb < 2; nb++)
                ldsm_x4(sbh + (u32)(nb * 2304) + ko, bb[nb]);
            #pragma unroll
            for (int mi = 0; mi < 4; mi++)
                #pragma unroll
                for (int ni = 0; ni < 4; ni++)
                    mma_f16(c[mi][ni], ah[mi], &bb[ni >> 1][(ni & 1) * 2]);
        }
        __syncthreads();
    }

    const int r0 = wm*64 + (lane >> 2);
    const int cc0 = wn*32 + (lane & 3)*2;

    #pragma unroll
    for (int mi = 0; mi < 4; mi++) {
        #pragma unroll
        for (int half = 0; half < 2; half++) {
            const size_t orow = arow + r0 + mi*16 + half*8;
            #pragma unroll
            for (int ni = 0; ni < 4; ni++) {
                const size_t ncol = brow + cc0 + ni*8;
                float v0 = c[mi][ni][half*2+0] + bias[ncol];
                float v1 = c[mi][ni][half*2+1] + bias[ncol+1];
                if (mode == 2) {
                    v0 = fmaxf(v0, 0.f); v1 = fmaxf(v1, 0.f);
                    *(__half2*)(oh + orow*(size_t)Ntot + ncol) = __floats2half2_rn(v0, v1);
                } else if (mode == 4) {
                    *(__half2*)(oh + orow*(size_t)Ntot + ncol) = __floats2half2_rn(v0, v1);
                } else if (mode == 5) {
                    u32 raw; memcpy(&raw, resid16 + orow*(size_t)Ntot + ncol, 4);
                    __half2 rv; memcpy(&rv, &raw, 4);
                    float2 rf = __half22float2(rv);
                    *(__half2*)(oh + orow*(size_t)Ntot + ncol) =
                        __floats2half2_rn(v0 + rf.x, v1 + rf.y);
                } else {  // mode 3
                    u32 raw; memcpy(&raw, resid16 + orow*(size_t)Ntot + ncol, 4);
                    __half2 rv; memcpy(&rv, &raw, 4);
                    float2 rf = __half22float2(rv);
                    float2 o; o.x = v0 + rf.x; o.y = v1 + rf.y;
                    *(float2*)(outf + orow*(size_t)Ntot + ncol) = o;
                }
            }
        }
    }
}

// ======================= HMMA attention core =======================
#define ATS 112
#define AARR 7168

__global__ __launch_bounds__(128) void attn_kernel()
{
    __shared__ __align__(16) char sm[3*AARR];
    const u32 smb = smem_u32(sm);

    const int tid = threadIdx.x;
    const int wid = tid >> 5;
    const int lane = tid & 31;
    const int bh = blockIdx.x;
    const int b = bh >> 3;
    const int h = bh & 7;
    const float kScale = 0.14433756729740643f;   // 48^-0.5

    {
        const __half* src = g_qkv16 + (size_t)(b*TT) * NQKV + h*144;
        #pragma unroll
        for (int i = 0; i < 9; i++) {
            int s = tid + (i << 7);
            int r = s / 18;
            int j = s - r*18;
            int arr = j / 6;
            int jj = j - arr*6;
            cp16(smb + arr*AARR + r*ATS + jj*16,
                 src + (size_t)r*NQKV + j*8);
        }
        CP_COMMIT(); CP_WAIT(0);
        __syncthreads();
    }

    const u32 smQ = smb, smK = smb + AARR, smV = smb + 2*AARR;

    const u32 a_addr  = smQ + (u32)((16*wid + (lane & 15)) * ATS + (lane >> 4) * 16);
    const u32 kb_addr = smK + (u32)((((lane & 7) | ((lane >> 1) & 8))) * ATS
                                    + ((lane >> 3) & 1) * 16);
    const int vg = lane >> 3;
    const u32 vb_addr = smV + (u32)(((vg & 1) * 8 + (lane & 7)) * ATS + (vg >> 1) * 16);

    float sc[8][4];
    #pragma unroll
    for (int nb = 0; nb < 8; nb++)
        #pragma unroll
        for (int j = 0; j < 4; j++) sc[nb][j] = 0.f;

    {
        u32 aq[3][4];
        #pragma unroll
        for (int ks = 0; ks < 3; ks++) ldsm_x4(a_addr + ks*32, aq[ks]);
        #pragma unroll
        for (int np = 0; np < 4; np++) {
            #pragma unroll
            for (int ks = 0; ks < 3; ks++) {
                u32 bb[4];
                ldsm_x4(kb_addr + (u32)(np*16*ATS) + ks*32, bb);
                mma_f16(sc[2*np],   aq[ks], &bb[0]);
                mma_f16(sc[2*np+1], aq[ks], &bb[2]);
            }
        }
    }

    const int r_lo = 16*wid + (lane >> 2);
    const int c0 = (lane & 3) * 2;
    float mlo = -1e30f, mhi = -1e30f;
    #pragma unroll
    for (int nb = 0; nb < 8; nb++) {
        const int cA = nb*8 + c0, cB = cA + 1;
        if (cA > r_lo)     sc[nb][0] = -1e30f;
        if (cB > r_lo)     sc[nb][1] = -1e30f;
        if (cA > r_lo + 8) sc[nb][2] = -1e30f;
        if (cB > r_lo + 8) sc[nb][3] = -1e30f;
        mlo = fmaxf(mlo, fmaxf(sc[nb][0], sc[nb][1]));
        mhi = fmaxf(mhi, fmaxf(sc[nb][2], sc[nb][3]));
    }
    #pragma unroll
    for (int o = 1; o <= 2; o <<= 1) {
        mlo = fmaxf(mlo, __shfl_xor_sync(0xffffffffu, mlo, o));
        mhi = fmaxf(mhi, __shfl_xor_sync(0xffffffffu, mhi, o));
    }
    mlo *= kScale; mhi *= kScale;
    float slo = 0.f, shi = 0.f;
    #pragma unroll
    for (int nb = 0; nb < 8; nb++) {
        sc[nb][0] = __expf(sc[nb][0]*kScale - mlo);
        sc[nb][1] = __expf(sc[nb][1]*kScale - mlo);
        sc[nb][2] = __expf(sc[nb][2]*kScale - mhi);
        sc[nb][3] = __expf(sc[nb][3]*kScale - mhi);
        slo += sc[nb][0] + sc[nb][1];
        shi += sc[nb][2] + sc[nb][3];
    }
    #pragma unroll
    for (int o = 1; o <= 2; o <<= 1) {
        slo += __shfl_xor_sync(0xffffffffu, slo, o);
        shi += __shfl_xor_sync(0xffffffffu, shi, o);
    }
    const float ilo = 1.0f / slo, ihi = 1.0f / shi;
    #pragma unroll
    for (int nb = 0; nb < 8; nb++) {
        sc[nb][0] *= ilo; sc[nb][1] *= ilo;
        sc[nb][2] *= ihi; sc[nb][3] *= ihi;
    }

    u32 pf[4][4];
    #pragma unroll
    for (int ks = 0; ks < 4; ks++) {
        const int t0 = 2*ks, t1 = 2*ks + 1;
        pf[ks][0] = h2u(sc[t0][0], sc[t0][1]);
        pf[ks][1] = h2u(sc[t0][2], sc[t0][3]);
        pf[ks][2] = h2u(sc[t1][0], sc[t1][1]);
        pf[ks][3] = h2u(sc[t1][2], sc[t1][3]);
    }

    float oc[6][4];
    #pragma unroll
    for (int nb = 0; nb < 6; nb++)
        #pragma unroll
        for (int j = 0; j < 4; j++) oc[nb][j] = 0.f;

    #pragma unroll
    for (int ks = 0; ks < 4; ks++) {
        #pragma unroll
        for (int np = 0; np < 3; np++) {
            u32 vb[4];
            ldsm_x4_t(vb_addr + (u32)(ks*16*ATS) + (u32)(np*32), vb);
            mma_f16(oc[2*np],   pf[ks], &vb[0]);
            mma_f16(oc[2*np+1], pf[ks], &vb[2]);
        }
    }

    #pragma unroll
    for (int nb = 0; nb < 6; nb++) {
        #pragma unroll
        for (int half = 0; half < 2; half++) {
            const int r = r_lo + 8*half;
            const size_t row = (size_t)(b*TT + r);
            const int col = h*HS + nb*8 + c0;
            *(__half2*)(g_at16 + row*DD + col) =
                __floats2half2_rn(oc[nb][half*2+0], oc[nb][half*2+1]);
        }
    }
}

// ======================= host launcher =======================
template <typename T>
static void* sym_addr(T& sym) { void* p = nullptr; cudaGetSymbolAddress(&p, sym); return p; }

extern "C" void kernel_launch(void* const* d_in, const int* in_sizes, int n_in,
                              void* d_out, int out_size) {
    const float* x   = (const float*)d_in[0];
    const float* wq  = (const float*)d_in[1];
    const float* bq  = (const float*)d_in[2];
    const float* wk  = (const float*)d_in[3];
    const float* bk  = (const float*)d_in[4];
    const float* wv  = (const float*)d_in[5];
    const float* bv  = (const float*)d_in[6];
    const float* wo  = (const float*)d_in[7];
    const float* bo  = (const float*)d_in[8];
    const float* w1  = (const float*)d_in[9];
    const float* b1  = (const float*)d_in[10];
    const float* w2  = (const float*)d_in[11];
    const float* b2  = (const float*)d_in[12];
    const float* g1  = (const float*)d_in[13];
    const float* be1 = (const float*)d_in[14];
    const float* g2  = (const float*)d_in[15];
    const float* be2 = (const float*)d_in[16];
    float* out = (float*)d_out;

    const int nb = in_sizes[0] / (TT * DD);
    const int M  = nb * TT;
    const int Mtiles = M / 128;

    __half* p_h16   = (__half*)sym_addr(g_h16);
    __half* p_qkv16 = (__half*)sym_addr(g_qkv16);
    __half* p_at16  = (__half*)sym_addr(g_at16);
    __half* p_hs16  = (__half*)sym_addr(g_hs16);
    __half* p_h216  = (__half*)sym_addr(g_h216);
    __half* p_r16   = (__half*)sym_addr(g_r16);
    __half* p_wqkv  = (__half*)sym_addr(g_wqkv);
    __half* p_wot   = (__half*)sym_addr(g_wot);
    __half* p_w1t   = (__half*)sym_addr(g_w1t);
    __half* p_w2t   = (__half*)sym_addr(g_w2t);
    float* p_bqkv   = (float*)sym_addr(g_bqkv);

    cudaFuncSetAttribute(gemm_kernel, cudaFuncAttributeMaxDynamicSharedMemorySize, GSM_TOTAL);

    // 1. weight fp16 convert / transpose
    split_weights_kernel<<<1024, 256>>>(wq, bq, wk, bk, wv, bv, wo, w1, w2);

    // 2. LN1: h16 = fp16(ln(x))
    ln_f32_kernel<<<M/8, 256>>>(x, g1, be1, p_h16, M);

    // 3. QKV GEMM (fp16 out)
    gemm_kernel<<<Mtiles*9, 256, GSM_TOTAL>>>(
        p_h16, p_wqkv, p_bqkv, nullptr,
        nullptr, p_qkv16, DD, 9, NQKV, 4);

    // 4. HMMA attention core
    attn_kernel<<<nb*NH, 128>>>();

    // 5. wo GEMM with fused residual: hs16 = fp16(at @ wo + bo + h16)
    gemm_kernel<<<Mtiles*3, 256, GSM_TOTAL>>>(
        p_at16, p_wot, bo, p_h16,
        nullptr, p_hs16, DD, 3, DD, 5);

    // 6. LN2: h216 = fp16(ln(hs16))
    ln_f16_kernel<<<M/8, 256>>>(p_hs16, g2, be2, p_h216, M);

    // 7. FF1: r16 = fp16(relu(h216 @ w1 + b1))
    gemm_kernel<<<Mtiles*12, 256, GSM_TOTAL>>>(
        p_h216, p_w1t, b1, nullptr,
        nullptr, p_r16, DD, 12, FFD, 2);

    // 8. FF2: out = r16 @ w2 + b2 + h216  (fp32 out)
    gemm_kernel<<<Mtiles*3, 256, GSM_TOTAL>>>(
        p_r16, p_w2t, b2, p_h216,
        out, nullptr, FFD, 3, DD, 3);
}

// round 17
// speedup vs baseline: 1.0135x; 1.0061x over previous
#include <cuda_runtime.h>
#include <cuda_fp16.h>
#include <cstdint>
#include <cstring>

#define TT 64
#define DD 384
#define NH 8
#define HS 48
#define FFD 1536
#define NQKV 1152
#define NBMAX 2048
#define MROWS (NBMAX*TT)

typedef unsigned long long u64;
typedef unsigned int u32;

// ======================= device scratch buffers =======================
__device__ __half g_wqkv[NQKV*DD];
__device__ __half g_wot[DD*DD];
__device__ __half g_w1t[FFD*DD];
__device__ __half g_w2t[DD*FFD];
__device__ float g_bqkv[NQKV];
__device__ float g_h[(size_t)MROWS*DD];
__device__ __half g_h16[(size_t)MROWS*DD];
__device__ __half g_qkv16[(size_t)MROWS*NQKV];
__device__ __half g_at16[(size_t)MROWS*DD];
__device__ float g_hs[(size_t)MROWS*DD];
__device__ float g_h2[(size_t)MROWS*DD];
__device__ __half g_h216[(size_t)MROWS*DD];
__device__ __half g_r16[(size_t)MROWS*FFD];

// ======================= helpers =======================
__device__ __forceinline__ u32 h2u(float a, float b) {
    __half2 h = __floats2half2_rn(a, b);
    u32 r; memcpy(&r, &h, 4); return r;
}
__device__ __forceinline__ u32 smem_u32(const void* p) {
    u32 a; asm("{ .reg .u64 t; cvta.to.shared.u64 t, %1; cvt.u32.u64 %0, t; }" : "=r"(a) : "l"(p));
    return a;
}
__device__ __forceinline__ void cp16(u32 dst, const void* src) {
    asm volatile("cp.async.cg.shared.global [%0], [%1], 16;" :: "r"(dst), "l"(src));
}
#define CP_COMMIT()  asm volatile("cp.async.commit_group;" ::: "memory")
#define CP_WAIT(n)   asm volatile("cp.async.wait_group %0;" :: "n"(n) : "memory")

__device__ __forceinline__ void ldsm_x4(u32 addr, u32* r) {
    asm volatile("ldmatrix.sync.aligned.m8n8.x4.shared.b16 {%0,%1,%2,%3}, [%4];"
        : "=r"(r[0]), "=r"(r[1]), "=r"(r[2]), "=r"(r[3]) : "r"(addr));
}
__device__ __forceinline__ void ldsm_x4_t(u32 addr, u32* r) {
    asm volatile("ldmatrix.sync.aligned.m8n8.x4.trans.shared.b16 {%0,%1,%2,%3}, [%4];"
        : "=r"(r[0]), "=r"(r[1]), "=r"(r[2]), "=r"(r[3]) : "r"(addr));
}
__device__ __forceinline__ void mma_f16(float* c, const u32* a, const u32* b) {
    asm volatile("mma.sync.aligned.m16n8k16.row.col.f32.f16.f16.f32 "
        "{%0,%1,%2,%3}, {%4,%5,%6,%7}, {%8,%9}, {%0,%1,%2,%3};"
        : "+f"(c[0]), "+f"(c[1]), "+f"(c[2]), "+f"(c[3])
        : "r"(a[0]), "r"(a[1]), "r"(a[2]), "r"(a[3]), "r"(b[0]), "r"(b[1]));
}

// ======================= weight fp16 convert / transpose =======================
__global__ void split_weights_kernel(
    const float* __restrict__ wq, const float* __restrict__ bq,
    const float* __restrict__ wk, const float* __restrict__ bk,
    const float* __restrict__ wv, const float* __restrict__ bv,
    const float* __restrict__ wo, const float* __restrict__ w1,
    const float* __restrict__ w2)
{
    const int stride = gridDim.x * blockDim.x;
    const int t0 = blockIdx.x * blockDim.x + threadIdx.x;
    for (int i = t0; i < NQKV*DD; i += stride) {
        int n = i / DD, k = i - n*DD;
        int h = n / 144, rm = n - h*144, m = rm / 48, e = rm - m*48;
        const float* src = (m==0) ? wq : ((m==1) ? wk : wv);
        g_wqkv[i] = __float2half_rn(src[((size_t)(h*DD + k))*HS + e]);
    }
    for (int i = t0; i < DD*DD; i += stride) {
        int n = i / DD, k = i - n*DD;
        g_wot[i] = __float2half_rn(wo[(size_t)k*DD + n]);
    }
    for (int i = t0; i < FFD*DD; i += stride) {
        int n = i / DD, k = i - n*DD;
        g_w1t[i] = __float2half_rn(w1[(size_t)k*FFD + n]);
    }
    for (int i = t0; i < DD*FFD; i += stride) {
        int n = i / FFD, k = i - n*FFD;
        g_w2t[i] = __float2half_rn(w2[(size_t)k*DD + n]);
    }
    for (int i = t0; i < NQKV; i += stride) {
        int h = i / 144, rm = i - h*144, m = rm / 48, e = rm - m*48;
        g_bqkv[i] = (m==0 ? bq : (m==1 ? bk : bv))[h*HS + e];
    }
}

// ======================= layernorm + fp16 out =======================
__global__ __launch_bounds__(256) void ln_kernel(
    const float* __restrict__ in1,
    const float* __restrict__ gg, const float* __restrict__ bb,
    float* __restrict__ outf, __half* __restrict__ oh,
    int nrows)
{
    int r = blockIdx.x*8 + (threadIdx.x >> 5);
    int l = threadIdx.x & 31;
    if (r >= nrows) return;
    size_t ro = (size_t)r * DD;
    float v[12]; float s1 = 0.f, s2 = 0.f;
    #pragma unroll
    for (int jt = 0; jt < 3; jt++) {
        int c = jt*128 + 4*l;
        float4 a = *(const float4*)(in1 + ro + c);
        v[4*jt+0]=a.x; v[4*jt+1]=a.y; v[4*jt+2]=a.z; v[4*jt+3]=a.w;
    }
    #pragma unroll
    for (int i = 0; i < 12; i++) { s1 += v[i]; s2 += v[i]*v[i]; }
    #pragma unroll
    for (int o = 16; o > 0; o >>= 1) {
        s1 += __shfl_xor_sync(0xffffffffu, s1, o);
        s2 += __shfl_xor_sync(0xffffffffu, s2, o);
    }
    float mean = s1 * (1.0f/384.0f);
    float var  = s2 * (1.0f/384.0f) - mean*mean;
    float rstd = rsqrtf(var + 1e-5f);
    #pragma unroll
    for (int jt = 0; jt < 3; jt++) {
        int c = jt*128 + 4*l;
        float4 gv = *(const float4*)(gg + c);
        float4 bv = *(const float4*)(bb + c);
        float y0 = (v[4*jt+0]-mean)*rstd*gv.x + bv.x;
        float y1 = (v[4*jt+1]-mean)*rstd*gv.y + bv.y;
        float y2 = (v[4*jt+2]-mean)*rstd*gv.z + bv.z;
        float y3 = (v[4*jt+3]-mean)*rstd*gv.w + bv.w;
        if (outf) *(float4*)(outf + ro + c) = make_float4(y0, y1, y2, y3);
        *(__half2*)(oh + ro + c)     = __floats2half2_rn(y0, y1);
        *(__half2*)(oh + ro + c + 2) = __floats2half2_rn(y2, y3);
    }
}

// ======================= fp16 GEMM: 8 warps, K-chunk 64, 3-stage pipeline =======================
// mode 0: outf = D + bias
// mode 2: oh = fp16(relu(D + bias))
// mode 3: outf = D + bias + resid
// mode 4: oh = fp16(D + bias)
#define ARR_BYTES 18432                  // 128 rows * 144 B
#define STG_BYTES (2*ARR_BYTES)          // 36864
#define GSM_TOTAL (3*STG_BYTES)          // 110592 (3 stages)

__global__ __launch_bounds__(256, 2) void gemm_kernel(
    const __half* __restrict__ Ah, const __half* __restrict__ Bh,
    const float* __restrict__ bias, const float* __restrict__ resid,
    float* __restrict__ outf, __half* __restrict__ oh,
    int K, int Ntiles, int Ntot, int mode)
{
    extern __shared__ char smem[];
    const u32 smem_base = smem_u32(smem);
    const int tid = threadIdx.x;
    const int wid = tid >> 5;
    const int lane = tid & 31;

    const int mt = blockIdx.x / Ntiles;
    const int nt = blockIdx.x - mt * Ntiles;
    const size_t arow = (size_t)mt * 128;
    const size_t brow = (size_t)nt * 128;

    const __half* Abase = Ah + arow * (size_t)K;
    const __half* Bbase = Bh + brow * (size_t)K;

    const int wm = wid & 1;
    const int wn = wid >> 1;

    const u32 a_off = (u32)((wm*64 + (lane & 15)) * 144 + (lane >> 4) * 16);
    const u32 b_off = (u32)((wn*32 + ((lane & 7) | ((lane >> 1) & 8))) * 144
                            + ((lane >> 3) & 1) * 16);

    float c[4][4][4];
    #pragma unroll
    for (int mi = 0; mi < 4; mi++)
        #pragma unroll
        for (int ni = 0; ni < 4; ni++)
            #pragma unroll
            for (int j = 0; j < 4; j++) c[mi][ni][j] = 0.f;

    const int nc = K >> 6;   // K/64 chunks (>= 6 in all uses)

    auto load_chunk = [&](int stage, int cc) {
        const u32 sb = smem_base + (u32)stage * STG_BYTES;
        const int c0 = cc << 6;
        #pragma unroll
        for (int i = 0; i < 8; i++) {
            int s = tid + (i << 8);
            int arr = s >> 10;             // 0..1
            int within = s & 1023;
            int r   = within >> 3;
            int c16 = within & 7;
            const __half* bp = (arr == 0) ? Abase : Bbase;
            const void* src = bp + (size_t)r * K + c0 + (c16 << 3);
            u32 dst = sb + arr * ARR_BYTES + (u32)(r * 144 + (c16 << 4));
            cp16(dst, src);
        }
        CP_COMMIT();
    };

    // prologue: prefetch 2 chunks
    load_chunk(0, 0);
    load_chunk(1, 1);

    int stage = 0;
    for (int cc = 0; cc < nc; cc++) {
        if (cc + 1 < nc) { CP_WAIT(1); }
        else             { CP_WAIT(0); }
        __syncthreads();   // chunk cc resident; all warps done with chunk cc-1

        // prefetch chunk cc+2 into the stage freed by chunk cc-1
        if (cc + 2 < nc) {
            int nstage = stage + 2; if (nstage >= 3) nstage -= 3;
            load_chunk(nstage, cc + 2);
        }

        const u32 sb = smem_base + (u32)stage * STG_BYTES;
        const u32 sa = sb + a_off;
        const u32 sbh = sb + ARR_BYTES + b_off;

        #pragma unroll
        for (int ks = 0; ks < 4; ks++) {
            const u32 ko = (u32)(ks * 32);
            u32 ah[4][4], bb[2][4];
            #pragma unroll
            for (int mi = 0; mi < 4; mi++)
                ldsm_x4(sa + (u32)(mi * 2304) + ko, ah[mi]);
            #pragma unroll
            for (int nb = 0; nb < 2; nb++)
                ldsm_x4(sbh + (u32)(nb * 2304) + ko, bb[nb]);
            #pragma unroll
            for (int mi = 0; mi < 4; mi++)
                #pragma unroll
                for (int ni = 0; ni < 4; ni++)
                    mma_f16(c[mi][ni], ah[mi], &bb[ni >> 1][(ni & 1) * 2]);
        }
        if (++stage == 3) stage = 0;
    }

    const int r0 = wm*64 + (lane >> 2);
    const int cc0 = wn*32 + (lane & 3)*2;

    #pragma unroll
    for (int mi = 0; mi < 4; mi++) {
        #pragma unroll
        for (int half = 0; half < 2; half++) {
            const size_t orow = arow + r0 + mi*16 + half*8;
            #pragma unroll
            for (int ni = 0; ni < 4; ni++) {
                const size_t ncol = brow + cc0 + ni*8;
                float v0 = c[mi][ni][half*2+0] + bias[ncol];
                float v1 = c[mi][ni][half*2+1] + bias[ncol+1];
                if (mode == 2) {
                    v0 = fmaxf(v0, 0.f); v1 = fmaxf(v1, 0.f);
                    *(__half2*)(oh + orow*(size_t)Ntot + ncol) = __floats2half2_rn(v0, v1);
                } else if (mode == 4) {
                    *(__half2*)(oh + orow*(size_t)Ntot + ncol) = __floats2half2_rn(v0, v1);
                } else if (mode == 3) {
                    const float* rp = resid + orow*(size_t)Ntot + ncol;
                    float2 o; o.x = v0 + rp[0]; o.y = v1 + rp[1];
                    *(float2*)(outf + orow*(size_t)Ntot + ncol) = o;
                } else {
                    float2 o; o.x = v0; o.y = v1;
                    *(float2*)(outf + orow*(size_t)Ntot + ncol) = o;
                }
            }
        }
    }
}

// ======================= HMMA attention core =======================
#define ATS 112
#define AARR 7168

__global__ __launch_bounds__(128) void attn_kernel()
{
    __shared__ __align__(16) char sm[3*AARR];
    const u32 smb = smem_u32(sm);

    const int tid = threadIdx.x;
    const int wid = tid >> 5;
    const int lane = tid & 31;
    const int bh = blockIdx.x;
    const int b = bh >> 3;
    const int h = bh & 7;
    const float kScale = 0.14433756729740643f;   // 48^-0.5

    {
        const __half* src = g_qkv16 + (size_t)(b*TT) * NQKV + h*144;
        #pragma unroll
        for (int i = 0; i < 9; i++) {
            int s = tid + (i << 7);
            int r = s / 18;
            int j = s - r*18;
            int arr = j / 6;
            int jj = j - arr*6;
            cp16(smb + arr*AARR + r*ATS + jj*16,
                 src + (size_t)r*NQKV + j*8);
        }
        CP_COMMIT(); CP_WAIT(0);
        __syncthreads();
    }

    const u32 smQ = smb, smK = smb + AARR, smV = smb + 2*AARR;

    const u32 a_addr  = smQ + (u32)((16*wid + (lane & 15)) * ATS + (lane >> 4) * 16);
    const u32 kb_addr = smK + (u32)((((lane & 7) | ((lane >> 1) & 8))) * ATS
                                    + ((lane >> 3) & 1) * 16);
    const int vg = lane >> 3;
    const u32 vb_addr = smV + (u32)(((vg & 1) * 8 + (lane & 7)) * ATS + (vg >> 1) * 16);

    float sc[8][4];
    #pragma unroll
    for (int nb = 0; nb < 8; nb++)
        #pragma unroll
        for (int j = 0; j < 4; j++) sc[nb][j] = 0.f;

    {
        u32 aq[3][4];
        #pragma unroll
        for (int ks = 0; ks < 3; ks++) ldsm_x4(a_addr + ks*32, aq[ks]);
        #pragma unroll
        for (int np = 0; np < 4; np++) {
            #pragma unroll
            for (int ks = 0; ks < 3; ks++) {
                u32 bb[4];
                ldsm_x4(kb_addr + (u32)(np*16*ATS) + ks*32, bb);
                mma_f16(sc[2*np],   aq[ks], &bb[0]);
                mma_f16(sc[2*np+1], aq[ks], &bb[2]);
            }
        }
    }

    const int r_lo = 16*wid + (lane >> 2);
    const int c0 = (lane & 3) * 2;
    float mlo = -1e30f, mhi = -1e30f;
    #pragma unroll
    for (int nb = 0; nb < 8; nb++) {
        const int cA = nb*8 + c0, cB = cA + 1;
        if (cA > r_lo)     sc[nb][0] = -1e30f;
        if (cB > r_lo)     sc[nb][1] = -1e30f;
        if (cA > r_lo + 8) sc[nb][2] = -1e30f;
        if (cB > r_lo + 8) sc[nb][3] = -1e30f;
        mlo = fmaxf(mlo, fmaxf(sc[nb][0], sc[nb][1]));
        mhi = fmaxf(mhi, fmaxf(sc[nb][2], sc[nb][3]));
    }
    #pragma unroll
    for (int o = 1; o <= 2; o <<= 1) {
        mlo = fmaxf(mlo, __shfl_xor_sync(0xffffffffu, mlo, o));
        mhi = fmaxf(mhi, __shfl_xor_sync(0xffffffffu, mhi, o));
    }
    mlo *= kScale; mhi *= kScale;
    float slo = 0.f, shi = 0.f;
    #pragma unroll
    for (int nb = 0; nb < 8; nb++) {
        sc[nb][0] = __expf(sc[nb][0]*kScale - mlo);
        sc[nb][1] = __expf(sc[nb][1]*kScale - mlo);
        sc[nb][2] = __expf(sc[nb][2]*kScale - mhi);
        sc[nb][3] = __expf(sc[nb][3]*kScale - mhi);
        slo += sc[nb][0] + sc[nb][1];
        shi += sc[nb][2] + sc[nb][3];
    }
    #pragma unroll
    for (int o = 1; o <= 2; o <<= 1) {
        slo += __shfl_xor_sync(0xffffffffu, slo, o);
        shi += __shfl_xor_sync(0xffffffffu, shi, o);
    }
    const float ilo = 1.0f / slo, ihi = 1.0f / shi;
    #pragma unroll
    for (int nb = 0; nb < 8; nb++) {
        sc[nb][0] *= ilo; sc[nb][1] *= ilo;
        sc[nb][2] *= ihi; sc[nb][3] *= ihi;
    }

    u32 pf[4][4];
    #pragma unroll
    for (int ks = 0; ks < 4; ks++) {
        const int t0 = 2*ks, t1 = 2*ks + 1;
        pf[ks][0] = h2u(sc[t0][0], sc[t0][1]);
        pf[ks][1] = h2u(sc[t0][2], sc[t0][3]);
        pf[ks][2] = h2u(sc[t1][0], sc[t1][1]);
        pf[ks][3] = h2u(sc[t1][2], sc[t1][3]);
    }

    float oc[6][4];
    #pragma unroll
    for (int nb = 0; nb < 6; nb++)
        #pragma unroll
        for (int j = 0; j < 4; j++) oc[nb][j] = 0.f;

    #pragma unroll
    for (int ks = 0; ks < 4; ks++) {
        #pragma unroll
        for (int np = 0; np < 3; np++) {
            u32 vb[4];
            ldsm_x4_t(vb_addr + (u32)(ks*16*ATS) + (u32)(np*32), vb);
            mma_f16(oc[2*np],   pf[ks], &vb[0]);
            mma_f16(oc[2*np+1], pf[ks], &vb[2]);
        }
    }

    #pragma unroll
    for (int nb = 0; nb < 6; nb++) {
        #pragma unroll
        for (int half = 0; half < 2; half++) {
            const int r = r_lo + 8*half;
            const size_t row = (size_t)(b*TT + r);
            const int col = h*HS + nb*8 + c0;
            *(__half2*)(g_at16 + row*DD + col) =
                __floats2half2_rn(oc[nb][half*2+0], oc[nb][half*2+1]);
        }
    }
}

// ======================= host launcher =======================
template <typename T>
static void* sym_addr(T& sym) { void* p = nullptr; cudaGetSymbolAddress(&p, sym); return p; }

extern "C" void kernel_launch(void* const* d_in, const int* in_sizes, int n_in,
                              void* d_out, int out_size) {
    const float* x   = (const float*)d_in[0];
    const float* wq  = (const float*)d_in[1];
    const float* bq  = (const float*)d_in[2];
    const float* wk  = (const float*)d_in[3];
    const float* bk  = (const float*)d_in[4];
    const float* wv  = (const float*)d_in[5];
    const float* bv  = (const float*)d_in[6];
    const float* wo  = (const float*)d_in[7];
    const float* bo  = (const float*)d_in[8];
    const float* w1  = (const float*)d_in[9];
    const float* b1  = (const float*)d_in[10];
    const float* w2  = (const float*)d_in[11];
    const float* b2  = (const float*)d_in[12];
    const float* g1  = (const float*)d_in[13];
    const float* be1 = (const float*)d_in[14];
    const float* g2  = (const float*)d_in[15];
    const float* be2 = (const float*)d_in[16];
    float* out = (float*)d_out;

    const int nb = in_sizes[0] / (TT * DD);
    const int M  = nb * TT;
    const int Mtiles = M / 128;

    float* p_h      = (float*)sym_addr(g_h);
    __half* p_h16   = (__half*)sym_addr(g_h16);
    __half* p_qkv16 = (__half*)sym_addr(g_qkv16);
    __half* p_at16  = (__half*)sym_addr(g_at16);
    float* p_hs     = (float*)sym_addr(g_hs);
    float* p_h2     = (float*)sym_addr(g_h2);
    __half* p_h216  = (__half*)sym_addr(g_h216);
    __half* p_r16   = (__half*)sym_addr(g_r16);
    __half* p_wqkv  = (__half*)sym_addr(g_wqkv);
    __half* p_wot   = (__half*)sym_addr(g_wot);
    __half* p_w1t   = (__half*)sym_addr(g_w1t);
    __half* p_w2t   = (__half*)sym_addr(g_w2t);
    float* p_bqkv   = (float*)sym_addr(g_bqkv);

    cudaFuncSetAttribute(gemm_kernel, cudaFuncAttributeMaxDynamicSharedMemorySize, GSM_TOTAL);

    // 1. weight fp16 convert / transpose
    split_weights_kernel<<<1024, 256>>>(wq, bq, wk, bk, wv, bv, wo, w1, w2);

    // 2. LN1: h = ln(x) (fp32 for residual, fp16 for GEMM)
    ln_kernel<<<M/8, 256>>>(x, g1, be1, p_h, p_h16, M);

    // 3. QKV GEMM (fp16 out)
    gemm_kernel<<<Mtiles*9, 256, GSM_TOTAL>>>(
        p_h16, p_wqkv, p_bqkv, nullptr,
        nullptr, p_qkv16, DD, 9, NQKV, 4);

    // 4. HMMA attention core
    attn_kernel<<<nb*NH, 128>>>();

    // 5. wo GEMM with fused attention residual: hs = at @ wo + bo + h
    gemm_kernel<<<Mtiles*3, 256, GSM_TOTAL>>>(
        p_at16, p_wot, bo, p_h,
        p_hs, nullptr, DD, 3, DD, 3);

    // 6. LN2: h2 = ln(hs)
    ln_kernel<<<M/8, 256>>>(p_hs, g2, be2, p_h2, p_h216, M);

    // 7. FF1: r16 = fp16(relu(h2 @ w1 + b1))
    gemm_kernel<<<Mtiles*12, 256, GSM_TOTAL>>>(
        p_h216, p_w1t, b1, nullptr,
        nullptr, p_r16, DD, 12, FFD, 2);

    // 8. FF2: out = r16 @ w2 + b2 + h2
    gemm_kernel<<<Mtiles*3, 256, GSM_TOTAL>>>(
        p_r16, p_w2t, b2, p_h2,
        out, nullptr, FFD, 3, DD, 3);
}